// round 13
// baseline (speedup 1.0000x reference)
#include <cuda_runtime.h>
#include <cstdint>

// Shapes (fixed per reference): B=16, C=512, H=W=64, S=512
#define B_   16
#define C_   512
#define HW_  4096
#define S_   512
#define NCC  8          // C-chunks in pass kA
#define CCW  (C_/NCC)   // 64 channels per chunk

// Scratch (no allocation allowed — device globals; zero-initialized)
__device__ __align__(128) float g_part[NCC * B_ * HW_];  // 2 MB partial sumsq
__device__ __align__(128) float g_invrms[B_ * HW_];      // 262 KB
__device__ __align__(128) float g_style[B_ * 2 * C_];    // 64 KB
__device__ int g_tilecnt[B_ * 4];   // per-(b,tile) partial-done count (0..8)

#define GEMM_BLOCKS 256
#define WORK_BLOCKS 512   // 8 cc x 4 tiles x 16 b
#define COMB_BLOCKS 64    // 16 b x 4 tiles

// ---------------------------------------------------------------------------
// kA (fused, one launch):
//   [0,256):    style GEMM (first wave; latency hidden under streaming)
//   [256,768):  work: partial sumsq of x' = leaky(x + nw[c]*noise) over a
//               64-ch chunk x 1024-px tile; store partial, fence, signal.
//   [768,832):  combiners (scheduled last / run in the tail): spin until all
//               8 partials of (b,tile) are signalled, combine -> invrms.
//               Counter self-reset for graph replay (one combiner per slot).
// ---------------------------------------------------------------------------
__global__ __launch_bounds__(256) void kA(
    const float* __restrict__ x,
    const float* __restrict__ noise,
    const float* __restrict__ nw,
    const float* __restrict__ style,
    const float* __restrict__ W,
    const float* __restrict__ bias)
{
    const int tid = threadIdx.x;

    if (blockIdx.x < GEMM_BLOCKS) {
        // ----- style GEMM -----
        __shared__ float ss[S_];
        __shared__ float sp[256];
        const int gb = blockIdx.x;               // 0..255
        const int b = gb >> 4, chunk = gb & 15;  // 16 chunks of 64 cols
        for (int i = tid; i < S_; i += 256) ss[i] = style[b * S_ + i];
        __syncthreads();

        const int col = chunk * 64 + (tid & 63);
        const int k0  = (tid >> 6) * 128;        // 4 K-slices of 128
        float acc = 0.f;
#pragma unroll 8
        for (int k = k0; k < k0 + 128; k++)
            acc = fmaf(ss[k], __ldg(W + (size_t)k * 1024 + col), acc);
        sp[tid] = acc;
        __syncthreads();
        if (tid < 64)
            g_style[b * 1024 + col] = sp[tid] + sp[tid + 64] + sp[tid + 128]
                                    + sp[tid + 192] + __ldg(bias + col);
    } else if (blockIdx.x < GEMM_BLOCKS + WORK_BLOCKS) {
        // ----- work: partial sum-of-squares -----
        __shared__ float snw[CCW];
        const int bx   = blockIdx.x - GEMM_BLOCKS;  // 0..511
        const int cc   = bx & 7;
        const int tile = (bx >> 3) & 3;
        const int b    = bx >> 5;
        if (tid < CCW) snw[tid] = nw[cc * CCW + tid];
        __syncthreads();

        const int px = tile * 1024 + tid * 4;
        const float4 nz = *(const float4*)(noise + b * HW_ + px);
        const float* xp = x + ((size_t)b * C_ + cc * CCW) * HW_ + px;

        float4 acc = make_float4(0.f, 0.f, 0.f, 0.f);
#pragma unroll 8
        for (int c = 0; c < CCW; c++) {
            const float4 xv = __ldcs((const float4*)(xp + (size_t)c * HW_));
            const float w = snw[c];
            float v;
            v = fmaf(w, nz.x, xv.x); v = (v >= 0.f) ? v : 0.2f * v; acc.x = fmaf(v, v, acc.x);
            v = fmaf(w, nz.y, xv.y); v = (v >= 0.f) ? v : 0.2f * v; acc.y = fmaf(v, v, acc.y);
            v = fmaf(w, nz.z, xv.z); v = (v >= 0.f) ? v : 0.2f * v; acc.z = fmaf(v, v, acc.z);
            v = fmaf(w, nz.w, xv.w); v = (v >= 0.f) ? v : 0.2f * v; acc.w = fmaf(v, v, acc.w);
        }
        __stcg((float4*)(g_part + ((size_t)cc * B_ + b) * HW_ + px), acc);
        __threadfence();
        __syncthreads();
        if (tid == 0) atomicAdd(&g_tilecnt[b * 4 + tile], 1);
    } else {
        // ----- combiner: 8 partials -> invrms for (b, tile) -----
        const int bx = blockIdx.x - GEMM_BLOCKS - WORK_BLOCKS;  // 0..63
        const int b = bx >> 2, tile = bx & 3;
        const int slot = b * 4 + tile;

        if (tid == 0) {
            while (atomicAdd(&g_tilecnt[slot], 0) < NCC) __nanosleep(64);
        }
        __syncthreads();

        const int px = tile * 1024 + tid * 4;
        float4 s = make_float4(0.f, 0.f, 0.f, 0.f);
#pragma unroll
        for (int cc = 0; cc < NCC; cc++) {
            const float4 p = __ldcg((const float4*)(g_part + ((size_t)cc * B_ + b) * HW_ + px));
            s.x += p.x; s.y += p.y; s.z += p.z; s.w += p.w;
        }
        float4 r;
        r.x = rsqrtf(s.x * (1.f / (float)C_) + 1e-8f);
        r.y = rsqrtf(s.y * (1.f / (float)C_) + 1e-8f);
        r.z = rsqrtf(s.z * (1.f / (float)C_) + 1e-8f);
        r.w = rsqrtf(s.w * (1.f / (float)C_) + 1e-8f);
        *(float4*)(g_invrms + b * HW_ + px) = r;

        // Reset counter for next graph replay (one combiner owns this slot).
        __syncthreads();
        if (tid == 0) atomicExch(&g_tilecnt[slot], 0);
    }
}

// ---------------------------------------------------------------------------
// kB: one (b,c) plane per block (8192 blocks, 256 thr x 16 px) — R9 body.
//   y = leaky(x + nw[c]*noise) * invrms (regs), block-reduce mean/var,
//   out = y*(istd*scale) + (shift - mean*istd*scale)
// x via __ldcs (evict-first), out via __stcs; noise/invrms stay L2-hot.
// Launch boundary guarantees invrms visibility -> plain __ldg is safe here.
// ---------------------------------------------------------------------------
__global__ __launch_bounds__(256) void kB(
    const float* __restrict__ x,
    const float* __restrict__ noise,
    const float* __restrict__ nw,
    float* __restrict__ out)
{
    const int b = blockIdx.x >> 9;
    const int c = blockIdx.x & (C_ - 1);
    const size_t plane = ((size_t)b * C_ + c) * HW_;

    const float4* xp = (const float4*)(x + plane);
    const float4* np = (const float4*)(noise + (size_t)b * HW_);
    const float4* ip = (const float4*)(g_invrms + b * HW_);
    const float w = __ldg(nw + c);
    const int tid = threadIdx.x;

    float4 y[4];
    float sum = 0.f, sumsq = 0.f;

#pragma unroll
    for (int j = 0; j < 4; j++) {
        const int i = tid + j * 256;
        const float4 xv = __ldcs(xp + i);
        const float4 nv = __ldg(np + i);
        const float4 iv = __ldg(ip + i);
        float4 yv;
        float v;
        v = fmaf(w, nv.x, xv.x); v = (v >= 0.f) ? v : 0.2f * v; yv.x = v * iv.x;
        v = fmaf(w, nv.y, xv.y); v = (v >= 0.f) ? v : 0.2f * v; yv.y = v * iv.y;
        v = fmaf(w, nv.z, xv.z); v = (v >= 0.f) ? v : 0.2f * v; yv.z = v * iv.z;
        v = fmaf(w, nv.w, xv.w); v = (v >= 0.f) ? v : 0.2f * v; yv.w = v * iv.w;
        y[j] = yv;
        sum   += yv.x + yv.y + yv.z + yv.w;
        sumsq += yv.x * yv.x + yv.y * yv.y + yv.z * yv.z + yv.w * yv.w;
    }

    const int lane = tid & 31, warp = tid >> 5;
#pragma unroll
    for (int off = 16; off > 0; off >>= 1) {
        sum   += __shfl_xor_sync(0xFFFFFFFFu, sum,   off);
        sumsq += __shfl_xor_sync(0xFFFFFFFFu, sumsq, off);
    }
    __shared__ float s_sum[8], s_sq[8], s_stats[2];
    if (lane == 0) { s_sum[warp] = sum; s_sq[warp] = sumsq; }
    __syncthreads();
    if (tid == 0) {
        float ts = 0.f, tq = 0.f;
#pragma unroll
        for (int k = 0; k < 8; k++) { ts += s_sum[k]; tq += s_sq[k]; }
        const float mean = ts * (1.f / (float)HW_);
        const float var  = tq * (1.f / (float)HW_) - mean * mean;
        s_stats[0] = mean;
        s_stats[1] = rsqrtf(var + 1e-5f);
    }
    __syncthreads();
    const float mean = s_stats[0];
    const float istd = s_stats[1];

    const float scale = g_style[b * 1024 + c] + 1.f;   // s[:,0] + 1
    const float shift = g_style[b * 1024 + C_ + c];    // s[:,1]
    const float a = istd * scale;
    const float d = shift - mean * a;

    float4* op = (float4*)(out + plane);
#pragma unroll
    for (int j = 0; j < 4; j++) {
        const int i = tid + j * 256;
        const float4 yv = y[j];
        float4 ov;
        ov.x = fmaf(yv.x, a, d);
        ov.y = fmaf(yv.y, a, d);
        ov.z = fmaf(yv.z, a, d);
        ov.w = fmaf(yv.w, a, d);
        __stcs(op + i, ov);
    }
}

// ---------------------------------------------------------------------------
// Inputs (metadata order): x, noise, style, noise_weight, lin_W, lin_b
// Output: float32 [B, C, H, W]
// ---------------------------------------------------------------------------
extern "C" void kernel_launch(void* const* d_in, const int* in_sizes, int n_in,
                              void* d_out, int out_size)
{
    const float* x     = (const float*)d_in[0];
    const float* noise = (const float*)d_in[1];
    const float* style = (const float*)d_in[2];
    const float* nw    = (const float*)d_in[3];
    const float* lin_W = (const float*)d_in[4];
    const float* lin_b = (const float*)d_in[5];
    float* out = (float*)d_out;

    kA<<<GEMM_BLOCKS + WORK_BLOCKS + COMB_BLOCKS, 256>>>(x, noise, nw, style, lin_W, lin_b);
    kB<<<B_ * C_, 256>>>(x, noise, nw, out);
}

// round 14
// speedup vs baseline: 1.1900x; 1.1900x over previous
#include <cuda_runtime.h>
#include <cstdint>

// Shapes (fixed per reference): B=16, C=512, H=W=64, S=512
#define B_   16
#define C_   512
#define HW_  4096
#define S_   512
#define NCC  16         // C-chunks in pass kA
#define CCW  (C_/NCC)   // 32 channels per chunk

// Scratch (no allocation allowed — device globals)
__device__ __align__(128) float g_part[NCC * B_ * HW_];  // 4 MB partial sumsq
__device__ __align__(128) float g_invrms[B_ * HW_];      // 262 KB
__device__ __align__(128) float g_style[B_ * 2 * C_];    // 64 KB

#define GEMM_BLOCKS 256
#define WORK_BLOCKS 512   // 16 cc x 2 tiles x 16 b

// ---------------------------------------------------------------------------
// kA (fused): blocks [0,256): style GEMM (first wave, hidden under stream);
//   blocks [256,768): partial sumsq of x' = leaky(x + nw[c]*noise) over a
//   32-channel chunk, 2048-pixel tile. 256 thr x 8 px as TWO independent
//   float4 streams -> 2 outstanding loads per loop iter (MLP~16 @ unroll 8).
// ---------------------------------------------------------------------------
__global__ __launch_bounds__(256) void kA(
    const float* __restrict__ x,
    const float* __restrict__ noise,
    const float* __restrict__ nw,
    const float* __restrict__ style,
    const float* __restrict__ W,
    const float* __restrict__ bias)
{
    const int tid = threadIdx.x;

    if (blockIdx.x < GEMM_BLOCKS) {
        // ----- style GEMM -----
        __shared__ float ss[S_];
        __shared__ float sp[256];
        const int gb = blockIdx.x;               // 0..255
        const int b = gb >> 4, chunk = gb & 15;  // 16 chunks of 64 cols
        for (int i = tid; i < S_; i += 256) ss[i] = style[b * S_ + i];
        __syncthreads();

        const int col = chunk * 64 + (tid & 63);
        const int k0  = (tid >> 6) * 128;        // 4 K-slices of 128
        float acc = 0.f;
#pragma unroll 8
        for (int k = k0; k < k0 + 128; k++)
            acc = fmaf(ss[k], __ldg(W + (size_t)k * 1024 + col), acc);
        sp[tid] = acc;
        __syncthreads();
        if (tid < 64)
            g_style[b * 1024 + col] = sp[tid] + sp[tid + 64] + sp[tid + 128]
                                    + sp[tid + 192] + __ldg(bias + col);
    } else {
        __shared__ float snw[CCW];
        const int bx   = blockIdx.x - GEMM_BLOCKS;  // 0..511
        const int cc   = bx & 15;
        const int tile = (bx >> 4) & 1;             // 2 tiles of 2048 px
        const int b    = bx >> 5;
        if (tid < CCW) snw[tid] = nw[cc * CCW + tid];
        __syncthreads();

        const int px0 = tile * 2048 + tid * 4;      // stream 0
        const int px1 = px0 + 1024;                 // stream 1
        const float4 nz0 = *(const float4*)(noise + b * HW_ + px0);
        const float4 nz1 = *(const float4*)(noise + b * HW_ + px1);
        const float* xb = x + ((size_t)b * C_ + cc * CCW) * HW_;

        float4 a0 = make_float4(0.f, 0.f, 0.f, 0.f);
        float4 a1 = make_float4(0.f, 0.f, 0.f, 0.f);
#pragma unroll 8
        for (int c = 0; c < CCW; c++) {
            const float4 xv0 = __ldcs((const float4*)(xb + (size_t)c * HW_ + px0));
            const float4 xv1 = __ldcs((const float4*)(xb + (size_t)c * HW_ + px1));
            const float w = snw[c];
            float v;
            v = fmaf(w, nz0.x, xv0.x); v = (v >= 0.f) ? v : 0.2f * v; a0.x = fmaf(v, v, a0.x);
            v = fmaf(w, nz0.y, xv0.y); v = (v >= 0.f) ? v : 0.2f * v; a0.y = fmaf(v, v, a0.y);
            v = fmaf(w, nz0.z, xv0.z); v = (v >= 0.f) ? v : 0.2f * v; a0.z = fmaf(v, v, a0.z);
            v = fmaf(w, nz0.w, xv0.w); v = (v >= 0.f) ? v : 0.2f * v; a0.w = fmaf(v, v, a0.w);
            v = fmaf(w, nz1.x, xv1.x); v = (v >= 0.f) ? v : 0.2f * v; a1.x = fmaf(v, v, a1.x);
            v = fmaf(w, nz1.y, xv1.y); v = (v >= 0.f) ? v : 0.2f * v; a1.y = fmaf(v, v, a1.y);
            v = fmaf(w, nz1.z, xv1.z); v = (v >= 0.f) ? v : 0.2f * v; a1.z = fmaf(v, v, a1.z);
            v = fmaf(w, nz1.w, xv1.w); v = (v >= 0.f) ? v : 0.2f * v; a1.w = fmaf(v, v, a1.w);
        }
        float* pb = g_part + ((size_t)cc * B_ + b) * HW_;
        *(float4*)(pb + px0) = a0;
        *(float4*)(pb + px1) = a1;
    }
}

// ---------------------------------------------------------------------------
// kComb: combine 16 partials -> invrms. 128 blocks, 256 thr x 2 px (float2).
// ---------------------------------------------------------------------------
__global__ __launch_bounds__(256) void kComb()
{
    const int b = blockIdx.x >> 3, tile = blockIdx.x & 7;
    const int px = tile * 512 + threadIdx.x * 2;
    float2 s = make_float2(0.f, 0.f);
#pragma unroll
    for (int cc = 0; cc < NCC; cc++) {
        const float2 p = *(const float2*)(g_part + ((size_t)cc * B_ + b) * HW_ + px);
        s.x += p.x; s.y += p.y;
    }
    float2 r;
    r.x = rsqrtf(s.x * (1.f / (float)C_) + 1e-8f);
    r.y = rsqrtf(s.y * (1.f / (float)C_) + 1e-8f);
    *(float2*)(g_invrms + b * HW_ + px) = r;
}

// ---------------------------------------------------------------------------
// kB: one (b,c) plane per block (8192 blocks, 256 thr x 16 px) — R9 body.
//   y = leaky(x + nw[c]*noise) * invrms (regs), block-reduce mean/var,
//   out = y*(istd*scale) + (shift - mean*istd*scale)
// x via __ldcs (evict-first), out via __stcs; noise/invrms stay L2-hot.
// ---------------------------------------------------------------------------
__global__ __launch_bounds__(256) void kB(
    const float* __restrict__ x,
    const float* __restrict__ noise,
    const float* __restrict__ nw,
    float* __restrict__ out)
{
    const int b = blockIdx.x >> 9;
    const int c = blockIdx.x & (C_ - 1);
    const size_t plane = ((size_t)b * C_ + c) * HW_;

    const float4* xp = (const float4*)(x + plane);
    const float4* np = (const float4*)(noise + (size_t)b * HW_);
    const float4* ip = (const float4*)(g_invrms + b * HW_);
    const float w = __ldg(nw + c);
    const int tid = threadIdx.x;

    float4 y[4];
    float sum = 0.f, sumsq = 0.f;

#pragma unroll
    for (int j = 0; j < 4; j++) {
        const int i = tid + j * 256;
        const float4 xv = __ldcs(xp + i);
        const float4 nv = __ldg(np + i);
        const float4 iv = __ldg(ip + i);
        float4 yv;
        float v;
        v = fmaf(w, nv.x, xv.x); v = (v >= 0.f) ? v : 0.2f * v; yv.x = v * iv.x;
        v = fmaf(w, nv.y, xv.y); v = (v >= 0.f) ? v : 0.2f * v; yv.y = v * iv.y;
        v = fmaf(w, nv.z, xv.z); v = (v >= 0.f) ? v : 0.2f * v; yv.z = v * iv.z;
        v = fmaf(w, nv.w, xv.w); v = (v >= 0.f) ? v : 0.2f * v; yv.w = v * iv.w;
        y[j] = yv;
        sum   += yv.x + yv.y + yv.z + yv.w;
        sumsq += yv.x * yv.x + yv.y * yv.y + yv.z * yv.z + yv.w * yv.w;
    }

    const int lane = tid & 31, warp = tid >> 5;
#pragma unroll
    for (int off = 16; off > 0; off >>= 1) {
        sum   += __shfl_xor_sync(0xFFFFFFFFu, sum,   off);
        sumsq += __shfl_xor_sync(0xFFFFFFFFu, sumsq, off);
    }
    __shared__ float s_sum[8], s_sq[8], s_stats[2];
    if (lane == 0) { s_sum[warp] = sum; s_sq[warp] = sumsq; }
    __syncthreads();
    if (tid == 0) {
        float ts = 0.f, tq = 0.f;
#pragma unroll
        for (int k = 0; k < 8; k++) { ts += s_sum[k]; tq += s_sq[k]; }
        const float mean = ts * (1.f / (float)HW_);
        const float var  = tq * (1.f / (float)HW_) - mean * mean;
        s_stats[0] = mean;
        s_stats[1] = rsqrtf(var + 1e-5f);
    }
    __syncthreads();
    const float mean = s_stats[0];
    const float istd = s_stats[1];

    const float scale = g_style[b * 1024 + c] + 1.f;   // s[:,0] + 1
    const float shift = g_style[b * 1024 + C_ + c];    // s[:,1]
    const float a = istd * scale;
    const float d = shift - mean * a;

    float4* op = (float4*)(out + plane);
#pragma unroll
    for (int j = 0; j < 4; j++) {
        const int i = tid + j * 256;
        const float4 yv = y[j];
        float4 ov;
        ov.x = fmaf(yv.x, a, d);
        ov.y = fmaf(yv.y, a, d);
        ov.z = fmaf(yv.z, a, d);
        ov.w = fmaf(yv.w, a, d);
        __stcs(op + i, ov);
    }
}

// ---------------------------------------------------------------------------
// Inputs (metadata order): x, noise, style, noise_weight, lin_W, lin_b
// Output: float32 [B, C, H, W]
// ---------------------------------------------------------------------------
extern "C" void kernel_launch(void* const* d_in, const int* in_sizes, int n_in,
                              void* d_out, int out_size)
{
    const float* x     = (const float*)d_in[0];
    const float* noise = (const float*)d_in[1];
    const float* style = (const float*)d_in[2];
    const float* nw    = (const float*)d_in[3];
    const float* lin_W = (const float*)d_in[4];
    const float* lin_b = (const float*)d_in[5];
    float* out = (float*)d_out;

    kA<<<GEMM_BLOCKS + WORK_BLOCKS, 256>>>(x, noise, nw, style, lin_W, lin_b);
    kComb<<<128, 256>>>();
    kB<<<B_ * C_, 256>>>(x, noise, nw, out);
}

// round 15
// speedup vs baseline: 1.2215x; 1.0265x over previous
#include <cuda_runtime.h>
#include <cstdint>

// Shapes (fixed per reference): B=16, C=512, H=W=64, S=512
#define B_   16
#define C_   512
#define HW_  4096
#define S_   512
#define NCC  8          // C-chunks in pass kA
#define CCW  (C_/NCC)   // 64 channels per chunk

// Scratch (no allocation allowed — device globals)
__device__ __align__(128) float g_part[NCC * B_ * HW_];  // 2 MB partial sumsq
__device__ __align__(128) float g_invrms[B_ * HW_];      // 262 KB
__device__ __align__(128) float g_style[B_ * 2 * C_];    // 64 KB

#define GEMM_BLOCKS 256
#define WORK_BLOCKS 512   // 8 cc x 4 tiles x 16 b

// ---------------------------------------------------------------------------
// kA (fused): blocks [0,256): style GEMM (first wave; hidden under stream);
//   blocks [256,768): partial sumsq of x' = leaky(x + nw[c]*noise) over a
//   64-ch chunk x 1024-px tile; 256 thr x 4 px (float4).
//   Channel loop EXPLICITLY batches 8 loads before consuming -> MLP=8
//   guaranteed (same front-batched pattern that gets kB to 6.5 TB/s).
// ---------------------------------------------------------------------------
__global__ __launch_bounds__(256) void kA(
    const float* __restrict__ x,
    const float* __restrict__ noise,
    const float* __restrict__ nw,
    const float* __restrict__ style,
    const float* __restrict__ W,
    const float* __restrict__ bias)
{
    const int tid = threadIdx.x;

    if (blockIdx.x < GEMM_BLOCKS) {
        // ----- style GEMM -----
        __shared__ float ss[S_];
        __shared__ float sp[256];
        const int gb = blockIdx.x;               // 0..255
        const int b = gb >> 4, chunk = gb & 15;  // 16 chunks of 64 cols
        for (int i = tid; i < S_; i += 256) ss[i] = style[b * S_ + i];
        __syncthreads();

        const int col = chunk * 64 + (tid & 63);
        const int k0  = (tid >> 6) * 128;        // 4 K-slices of 128
        float acc = 0.f;
#pragma unroll 8
        for (int k = k0; k < k0 + 128; k++)
            acc = fmaf(ss[k], __ldg(W + (size_t)k * 1024 + col), acc);
        sp[tid] = acc;
        __syncthreads();
        if (tid < 64)
            g_style[b * 1024 + col] = sp[tid] + sp[tid + 64] + sp[tid + 128]
                                    + sp[tid + 192] + __ldg(bias + col);
    } else {
        __shared__ float snw[CCW];
        const int bx   = blockIdx.x - GEMM_BLOCKS;  // 0..511
        const int cc   = bx & 7;
        const int tile = (bx >> 3) & 3;
        const int b    = bx >> 5;
        if (tid < CCW) snw[tid] = nw[cc * CCW + tid];
        __syncthreads();

        const int px = tile * 1024 + tid * 4;
        const float4 nz = *(const float4*)(noise + b * HW_ + px);
        const float* xp = x + ((size_t)b * C_ + cc * CCW) * HW_ + px;

        float4 acc = make_float4(0.f, 0.f, 0.f, 0.f);
        for (int c0 = 0; c0 < CCW; c0 += 8) {
            // Phase 1: issue 8 independent LDG.128 back-to-back.
            float4 t[8];
#pragma unroll
            for (int j = 0; j < 8; j++)
                t[j] = __ldcs((const float4*)(xp + (size_t)(c0 + j) * HW_));
            // Phase 2: consume.
#pragma unroll
            for (int j = 0; j < 8; j++) {
                const float w = snw[c0 + j];
                float v;
                v = fmaf(w, nz.x, t[j].x); v = (v >= 0.f) ? v : 0.2f * v; acc.x = fmaf(v, v, acc.x);
                v = fmaf(w, nz.y, t[j].y); v = (v >= 0.f) ? v : 0.2f * v; acc.y = fmaf(v, v, acc.y);
                v = fmaf(w, nz.z, t[j].z); v = (v >= 0.f) ? v : 0.2f * v; acc.z = fmaf(v, v, acc.z);
                v = fmaf(w, nz.w, t[j].w); v = (v >= 0.f) ? v : 0.2f * v; acc.w = fmaf(v, v, acc.w);
            }
        }
        *(float4*)(g_part + ((size_t)cc * B_ + b) * HW_ + px) = acc;
    }
}

// ---------------------------------------------------------------------------
// kComb: combine 8 partials -> invrms. 64 blocks, 256 thr x 4 px (float4);
// 8 independent partial streams issued back-to-back (MLP=8).
// ---------------------------------------------------------------------------
__global__ __launch_bounds__(256) void kComb()
{
    const int b = blockIdx.x >> 2, tile = blockIdx.x & 3;
    const int px = tile * 1024 + threadIdx.x * 4;

    float4 p[NCC];
#pragma unroll
    for (int cc = 0; cc < NCC; cc++)
        p[cc] = *(const float4*)(g_part + ((size_t)cc * B_ + b) * HW_ + px);

    float4 s = make_float4(0.f, 0.f, 0.f, 0.f);
#pragma unroll
    for (int cc = 0; cc < NCC; cc++) {
        s.x += p[cc].x; s.y += p[cc].y; s.z += p[cc].z; s.w += p[cc].w;
    }
    float4 r;
    r.x = rsqrtf(s.x * (1.f / (float)C_) + 1e-8f);
    r.y = rsqrtf(s.y * (1.f / (float)C_) + 1e-8f);
    r.z = rsqrtf(s.z * (1.f / (float)C_) + 1e-8f);
    r.w = rsqrtf(s.w * (1.f / (float)C_) + 1e-8f);
    *(float4*)(g_invrms + b * HW_ + px) = r;
}

// ---------------------------------------------------------------------------
// kB: one (b,c) plane per block (8192 blocks, 256 thr x 16 px) — R9 body.
//   y = leaky(x + nw[c]*noise) * invrms (regs), block-reduce mean/var,
//   out = y*(istd*scale) + (shift - mean*istd*scale)
// x via __ldcs (evict-first), out via __stcs; noise/invrms stay L2-hot.
// ---------------------------------------------------------------------------
__global__ __launch_bounds__(256) void kB(
    const float* __restrict__ x,
    const float* __restrict__ noise,
    const float* __restrict__ nw,
    float* __restrict__ out)
{
    const int b = blockIdx.x >> 9;
    const int c = blockIdx.x & (C_ - 1);
    const size_t plane = ((size_t)b * C_ + c) * HW_;

    const float4* xp = (const float4*)(x + plane);
    const float4* np = (const float4*)(noise + (size_t)b * HW_);
    const float4* ip = (const float4*)(g_invrms + b * HW_);
    const float w = __ldg(nw + c);
    const int tid = threadIdx.x;

    float4 y[4];
    float sum = 0.f, sumsq = 0.f;

#pragma unroll
    for (int j = 0; j < 4; j++) {
        const int i = tid + j * 256;
        const float4 xv = __ldcs(xp + i);
        const float4 nv = __ldg(np + i);
        const float4 iv = __ldg(ip + i);
        float4 yv;
        float v;
        v = fmaf(w, nv.x, xv.x); v = (v >= 0.f) ? v : 0.2f * v; yv.x = v * iv.x;
        v = fmaf(w, nv.y, xv.y); v = (v >= 0.f) ? v : 0.2f * v; yv.y = v * iv.y;
        v = fmaf(w, nv.z, xv.z); v = (v >= 0.f) ? v : 0.2f * v; yv.z = v * iv.z;
        v = fmaf(w, nv.w, xv.w); v = (v >= 0.f) ? v : 0.2f * v; yv.w = v * iv.w;
        y[j] = yv;
        sum   += yv.x + yv.y + yv.z + yv.w;
        sumsq += yv.x * yv.x + yv.y * yv.y + yv.z * yv.z + yv.w * yv.w;
    }

    const int lane = tid & 31, warp = tid >> 5;
#pragma unroll
    for (int off = 16; off > 0; off >>= 1) {
        sum   += __shfl_xor_sync(0xFFFFFFFFu, sum,   off);
        sumsq += __shfl_xor_sync(0xFFFFFFFFu, sumsq, off);
    }
    __shared__ float s_sum[8], s_sq[8], s_stats[2];
    if (lane == 0) { s_sum[warp] = sum; s_sq[warp] = sumsq; }
    __syncthreads();
    if (tid == 0) {
        float ts = 0.f, tq = 0.f;
#pragma unroll
        for (int k = 0; k < 8; k++) { ts += s_sum[k]; tq += s_sq[k]; }
        const float mean = ts * (1.f / (float)HW_);
        const float var  = tq * (1.f / (float)HW_) - mean * mean;
        s_stats[0] = mean;
        s_stats[1] = rsqrtf(var + 1e-5f);
    }
    __syncthreads();
    const float mean = s_stats[0];
    const float istd = s_stats[1];

    const float scale = g_style[b * 1024 + c] + 1.f;   // s[:,0] + 1
    const float shift = g_style[b * 1024 + C_ + c];    // s[:,1]
    const float a = istd * scale;
    const float d = shift - mean * a;

    float4* op = (float4*)(out + plane);
#pragma unroll
    for (int j = 0; j < 4; j++) {
        const int i = tid + j * 256;
        const float4 yv = y[j];
        float4 ov;
        ov.x = fmaf(yv.x, a, d);
        ov.y = fmaf(yv.y, a, d);
        ov.z = fmaf(yv.z, a, d);
        ov.w = fmaf(yv.w, a, d);
        __stcs(op + i, ov);
    }
}

// ---------------------------------------------------------------------------
// Inputs (metadata order): x, noise, style, noise_weight, lin_W, lin_b
// Output: float32 [B, C, H, W]
// ---------------------------------------------------------------------------
extern "C" void kernel_launch(void* const* d_in, const int* in_sizes, int n_in,
                              void* d_out, int out_size)
{
    const float* x     = (const float*)d_in[0];
    const float* noise = (const float*)d_in[1];
    const float* style = (const float*)d_in[2];
    const float* nw    = (const float*)d_in[3];
    const float* lin_W = (const float*)d_in[4];
    const float* lin_b = (const float*)d_in[5];
    float* out = (float*)d_out;

    kA<<<GEMM_BLOCKS + WORK_BLOCKS, 256>>>(x, noise, nw, style, lin_W, lin_b);
    kComb<<<64, 256>>>();
    kB<<<B_ * C_, 256>>>(x, noise, nw, out);
}

// round 16
// speedup vs baseline: 1.2319x; 1.0085x over previous
#include <cuda_runtime.h>
#include <cstdint>

// Shapes (fixed per reference): B=16, C=512, H=W=64, S=512
#define B_   16
#define C_   512
#define HW_  4096
#define S_   512
#define NCC  8          // C-chunks in pass kA
#define CCW  (C_/NCC)   // 64 channels per chunk

// Scratch (no allocation allowed — device globals)
__device__ __align__(128) float g_part[NCC * B_ * HW_];  // 2 MB partial sumsq
__device__ __align__(128) float g_invrms[B_ * HW_];      // 262 KB
__device__ __align__(128) float g_style[B_ * 2 * C_];    // 64 KB

#define GEMM_BLOCKS 512   // 16 b x 32 col-chunks (32 cols each), 128 thr
#define WORK_BLOCKS 1024  // 8 cc x 8 tiles(512px) x 16 b, 128 thr

// ---------------------------------------------------------------------------
// kA (fused, 128-thread blocks — 1536 blocks all co-resident in ONE wave):
//   blocks [0,512):     style GEMM, 32 cols x 4 K-slices of 128 per block
//   blocks [512,1536):  partial sumsq of x' = leaky(x + nw[c]*noise) over a
//                       64-ch chunk x 512-px tile; 128 thr x 4 px (float4),
//                       8-deep explicit load batching.
// ---------------------------------------------------------------------------
__global__ __launch_bounds__(128) void kA(
    const float* __restrict__ x,
    const float* __restrict__ noise,
    const float* __restrict__ nw,
    const float* __restrict__ style,
    const float* __restrict__ W,
    const float* __restrict__ bias)
{
    const int tid = threadIdx.x;

    if (blockIdx.x < GEMM_BLOCKS) {
        // ----- style GEMM -----
        __shared__ float ss[S_];
        __shared__ float sp[128];
        const int gb = blockIdx.x;                // 0..511
        const int b = gb >> 5, chunk = gb & 31;   // 32 chunks of 32 cols
        for (int i = tid; i < S_; i += 128) ss[i] = style[b * S_ + i];
        __syncthreads();

        const int col = chunk * 32 + (tid & 31);
        const int k0  = (tid >> 5) * 128;         // 4 K-slices of 128
        float acc = 0.f;
#pragma unroll 8
        for (int k = k0; k < k0 + 128; k++)
            acc = fmaf(ss[k], __ldg(W + (size_t)k * 1024 + col), acc);
        sp[tid] = acc;
        __syncthreads();
        if (tid < 32)
            g_style[b * 1024 + col] = sp[tid] + sp[tid + 32] + sp[tid + 64]
                                    + sp[tid + 96] + __ldg(bias + col);
    } else {
        __shared__ float snw[CCW];
        const int bx   = blockIdx.x - GEMM_BLOCKS;  // 0..1023
        const int cc   = bx & 7;
        const int tile = (bx >> 3) & 7;             // 8 tiles of 512 px
        const int b    = bx >> 6;
        if (tid < CCW) snw[tid] = nw[cc * CCW + tid];
        __syncthreads();

        const int px = tile * 512 + tid * 4;
        const float4 nz = *(const float4*)(noise + b * HW_ + px);
        const float* xp = x + ((size_t)b * C_ + cc * CCW) * HW_ + px;

        float4 acc = make_float4(0.f, 0.f, 0.f, 0.f);
        for (int c0 = 0; c0 < CCW; c0 += 8) {
            float4 t[8];
#pragma unroll
            for (int j = 0; j < 8; j++)
                t[j] = __ldcs((const float4*)(xp + (size_t)(c0 + j) * HW_));
#pragma unroll
            for (int j = 0; j < 8; j++) {
                const float w = snw[c0 + j];
                float v;
                v = fmaf(w, nz.x, t[j].x); v = (v >= 0.f) ? v : 0.2f * v; acc.x = fmaf(v, v, acc.x);
                v = fmaf(w, nz.y, t[j].y); v = (v >= 0.f) ? v : 0.2f * v; acc.y = fmaf(v, v, acc.y);
                v = fmaf(w, nz.z, t[j].z); v = (v >= 0.f) ? v : 0.2f * v; acc.z = fmaf(v, v, acc.z);
                v = fmaf(w, nz.w, t[j].w); v = (v >= 0.f) ? v : 0.2f * v; acc.w = fmaf(v, v, acc.w);
            }
        }
        *(float4*)(g_part + ((size_t)cc * B_ + b) * HW_ + px) = acc;
    }
}

// ---------------------------------------------------------------------------
// kComb: combine 8 partials -> invrms. 64 blocks, 256 thr x 4 px (float4).
// ---------------------------------------------------------------------------
__global__ __launch_bounds__(256) void kComb()
{
    const int b = blockIdx.x >> 2, tile = blockIdx.x & 3;
    const int px = tile * 1024 + threadIdx.x * 4;

    float4 p[NCC];
#pragma unroll
    for (int cc = 0; cc < NCC; cc++)
        p[cc] = *(const float4*)(g_part + ((size_t)cc * B_ + b) * HW_ + px);

    float4 s = make_float4(0.f, 0.f, 0.f, 0.f);
#pragma unroll
    for (int cc = 0; cc < NCC; cc++) {
        s.x += p[cc].x; s.y += p[cc].y; s.z += p[cc].z; s.w += p[cc].w;
    }
    float4 r;
    r.x = rsqrtf(s.x * (1.f / (float)C_) + 1e-8f);
    r.y = rsqrtf(s.y * (1.f / (float)C_) + 1e-8f);
    r.z = rsqrtf(s.z * (1.f / (float)C_) + 1e-8f);
    r.w = rsqrtf(s.w * (1.f / (float)C_) + 1e-8f);
    *(float4*)(g_invrms + b * HW_ + px) = r;
}

// ---------------------------------------------------------------------------
// kB: one (b,c) plane per block (8192 blocks, 256 thr x 16 px) — R9 body.
//   y = leaky(x + nw[c]*noise) * invrms (regs), block-reduce mean/var,
//   out = y*(istd*scale) + (shift - mean*istd*scale)
// x via __ldcs (evict-first), out via __stcs; noise/invrms stay L2-hot.
// ---------------------------------------------------------------------------
__global__ __launch_bounds__(256) void kB(
    const float* __restrict__ x,
    const float* __restrict__ noise,
    const float* __restrict__ nw,
    float* __restrict__ out)
{
    const int b = blockIdx.x >> 9;
    const int c = blockIdx.x & (C_ - 1);
    const size_t plane = ((size_t)b * C_ + c) * HW_;

    const float4* xp = (const float4*)(x + plane);
    const float4* np = (const float4*)(noise + (size_t)b * HW_);
    const float4* ip = (const float4*)(g_invrms + b * HW_);
    const float w = __ldg(nw + c);
    const int tid = threadIdx.x;

    float4 y[4];
    float sum = 0.f, sumsq = 0.f;

#pragma unroll
    for (int j = 0; j < 4; j++) {
        const int i = tid + j * 256;
        const float4 xv = __ldcs(xp + i);
        const float4 nv = __ldg(np + i);
        const float4 iv = __ldg(ip + i);
        float4 yv;
        float v;
        v = fmaf(w, nv.x, xv.x); v = (v >= 0.f) ? v : 0.2f * v; yv.x = v * iv.x;
        v = fmaf(w, nv.y, xv.y); v = (v >= 0.f) ? v : 0.2f * v; yv.y = v * iv.y;
        v = fmaf(w, nv.z, xv.z); v = (v >= 0.f) ? v : 0.2f * v; yv.z = v * iv.z;
        v = fmaf(w, nv.w, xv.w); v = (v >= 0.f) ? v : 0.2f * v; yv.w = v * iv.w;
        y[j] = yv;
        sum   += yv.x + yv.y + yv.z + yv.w;
        sumsq += yv.x * yv.x + yv.y * yv.y + yv.z * yv.z + yv.w * yv.w;
    }

    const int lane = tid & 31, warp = tid >> 5;
#pragma unroll
    for (int off = 16; off > 0; off >>= 1) {
        sum   += __shfl_xor_sync(0xFFFFFFFFu, sum,   off);
        sumsq += __shfl_xor_sync(0xFFFFFFFFu, sumsq, off);
    }
    __shared__ float s_sum[8], s_sq[8], s_stats[2];
    if (lane == 0) { s_sum[warp] = sum; s_sq[warp] = sumsq; }
    __syncthreads();
    if (tid == 0) {
        float ts = 0.f, tq = 0.f;
#pragma unroll
        for (int k = 0; k < 8; k++) { ts += s_sum[k]; tq += s_sq[k]; }
        const float mean = ts * (1.f / (float)HW_);
        const float var  = tq * (1.f / (float)HW_) - mean * mean;
        s_stats[0] = mean;
        s_stats[1] = rsqrtf(var + 1e-5f);
    }
    __syncthreads();
    const float mean = s_stats[0];
    const float istd = s_stats[1];

    const float scale = g_style[b * 1024 + c] + 1.f;   // s[:,0] + 1
    const float shift = g_style[b * 1024 + C_ + c];    // s[:,1]
    const float a = istd * scale;
    const float d = shift - mean * a;

    float4* op = (float4*)(out + plane);
#pragma unroll
    for (int j = 0; j < 4; j++) {
        const int i = tid + j * 256;
        const float4 yv = y[j];
        float4 ov;
        ov.x = fmaf(yv.x, a, d);
        ov.y = fmaf(yv.y, a, d);
        ov.z = fmaf(yv.z, a, d);
        ov.w = fmaf(yv.w, a, d);
        __stcs(op + i, ov);
    }
}

// ---------------------------------------------------------------------------
// Inputs (metadata order): x, noise, style, noise_weight, lin_W, lin_b
// Output: float32 [B, C, H, W]
// ---------------------------------------------------------------------------
extern "C" void kernel_launch(void* const* d_in, const int* in_sizes, int n_in,
                              void* d_out, int out_size)
{
    const float* x     = (const float*)d_in[0];
    const float* noise = (const float*)d_in[1];
    const float* style = (const float*)d_in[2];
    const float* nw    = (const float*)d_in[3];
    const float* lin_W = (const float*)d_in[4];
    const float* lin_b = (const float*)d_in[5];
    float* out = (float*)d_out;

    kA<<<GEMM_BLOCKS + WORK_BLOCKS, 128>>>(x, noise, nw, style, lin_W, lin_b);
    kComb<<<64, 256>>>();
    kB<<<B_ * C_, 256>>>(x, noise, nw, out);
}

// round 17
// speedup vs baseline: 1.2341x; 1.0018x over previous
#include <cuda_runtime.h>
#include <cstdint>

// Shapes (fixed per reference): B=16, C=512, H=W=64, S=512
#define B_   16
#define C_   512
#define HW_  4096
#define S_   512
#define NCC  8          // C-chunks in pass kA
#define CCW  (C_/NCC)   // 64 channels per chunk

// Scratch (no allocation allowed — device globals; zero-initialized)
__device__ __align__(128) float g_part[NCC * B_ * HW_];  // 2 MB partial sumsq
__device__ __align__(128) float g_invrms[B_ * HW_];      // 262 KB
__device__ __align__(128) float g_style[B_ * 2 * C_];    // 64 KB
__device__ int g_ticket[B_ * 8];   // per-(b,tile) completion tickets (0..8)

#define GEMM_BLOCKS 512   // 16 b x 32 col-chunks (32 cols each), 128 thr
#define WORK_BLOCKS 1024  // 8 cc x 8 tiles(512px) x 16 b, 128 thr

// ---------------------------------------------------------------------------
// kA (fused, 128-thread blocks, single wave):
//   blocks [0,512):     style GEMM, 32 cols x 4 K-slices of 128 per block
//   blocks [512,1536):  partial sumsq of x' = leaky(x + nw[c]*noise) over a
//                       64-ch chunk x 512-px tile (4 px float4/thread,
//                       8-deep batched loads). After storing its partial,
//                       each block takes a ticket; the LAST of the 8 blocks
//                       for a (b,tile) slot combines the partials -> invrms
//                       (no dedicated spinner blocks, work lands in tail).
// ---------------------------------------------------------------------------
__global__ __launch_bounds__(128) void kA(
    const float* __restrict__ x,
    const float* __restrict__ noise,
    const float* __restrict__ nw,
    const float* __restrict__ style,
    const float* __restrict__ W,
    const float* __restrict__ bias)
{
    const int tid = threadIdx.x;

    if (blockIdx.x < GEMM_BLOCKS) {
        // ----- style GEMM -----
        __shared__ float ss[S_];
        __shared__ float sp[128];
        const int gb = blockIdx.x;                // 0..511
        const int b = gb >> 5, chunk = gb & 31;   // 32 chunks of 32 cols
        for (int i = tid; i < S_; i += 128) ss[i] = style[b * S_ + i];
        __syncthreads();

        const int col = chunk * 32 + (tid & 31);
        const int k0  = (tid >> 5) * 128;         // 4 K-slices of 128
        float acc = 0.f;
#pragma unroll 8
        for (int k = k0; k < k0 + 128; k++)
            acc = fmaf(ss[k], __ldg(W + (size_t)k * 1024 + col), acc);
        sp[tid] = acc;
        __syncthreads();
        if (tid < 32)
            g_style[b * 1024 + col] = sp[tid] + sp[tid + 32] + sp[tid + 64]
                                    + sp[tid + 96] + __ldg(bias + col);
    } else {
        __shared__ float snw[CCW];
        __shared__ int s_last;
        const int bx   = blockIdx.x - GEMM_BLOCKS;  // 0..1023
        const int cc   = bx & 7;
        const int tile = (bx >> 3) & 7;             // 8 tiles of 512 px
        const int b    = bx >> 6;
        if (tid < CCW) snw[tid] = nw[cc * CCW + tid];
        __syncthreads();

        const int px = tile * 512 + tid * 4;
        const float4 nz = *(const float4*)(noise + b * HW_ + px);
        const float* xp = x + ((size_t)b * C_ + cc * CCW) * HW_ + px;

        float4 acc = make_float4(0.f, 0.f, 0.f, 0.f);
        for (int c0 = 0; c0 < CCW; c0 += 8) {
            float4 t[8];
#pragma unroll
            for (int j = 0; j < 8; j++)
                t[j] = __ldcs((const float4*)(xp + (size_t)(c0 + j) * HW_));
#pragma unroll
            for (int j = 0; j < 8; j++) {
                const float w = snw[c0 + j];
                float v;
                v = fmaf(w, nz.x, t[j].x); v = (v >= 0.f) ? v : 0.2f * v; acc.x = fmaf(v, v, acc.x);
                v = fmaf(w, nz.y, t[j].y); v = (v >= 0.f) ? v : 0.2f * v; acc.y = fmaf(v, v, acc.y);
                v = fmaf(w, nz.z, t[j].z); v = (v >= 0.f) ? v : 0.2f * v; acc.z = fmaf(v, v, acc.z);
                v = fmaf(w, nz.w, t[j].w); v = (v >= 0.f) ? v : 0.2f * v; acc.w = fmaf(v, v, acc.w);
            }
        }
        *(float4*)(g_part + ((size_t)cc * B_ + b) * HW_ + px) = acc;

        // Ticket: last of the 8 cc-blocks for (b,tile) combines -> invrms.
        __threadfence();
        __syncthreads();
        const int slot = b * 8 + tile;
        if (tid == 0) {
            const int old = atomicAdd(&g_ticket[slot], 1);
            s_last = (old == NCC - 1);
        }
        __syncthreads();

        if (s_last) {
            float4 s = acc;   // own partial already in registers
#pragma unroll
            for (int k = 0; k < NCC; k++) {
                if (k == cc) continue;
                const float4 p = __ldcg((const float4*)(g_part + ((size_t)k * B_ + b) * HW_ + px));
                s.x += p.x; s.y += p.y; s.z += p.z; s.w += p.w;
            }
            float4 r;
            r.x = rsqrtf(s.x * (1.f / (float)C_) + 1e-8f);
            r.y = rsqrtf(s.y * (1.f / (float)C_) + 1e-8f);
            r.z = rsqrtf(s.z * (1.f / (float)C_) + 1e-8f);
            r.w = rsqrtf(s.w * (1.f / (float)C_) + 1e-8f);
            *(float4*)(g_invrms + b * HW_ + px) = r;
            __syncthreads();
            if (tid == 0) atomicExch(&g_ticket[slot], 0);   // replay-safe reset
        }
    }
}

// ---------------------------------------------------------------------------
// kB: one (b,c) plane per block (8192 blocks, 256 thr x 16 px) — R9 body.
//   y = leaky(x + nw[c]*noise) * invrms (regs), block-reduce mean/var,
//   out = y*(istd*scale) + (shift - mean*istd*scale)
// x via __ldcs (evict-first), out via __stcs; noise/invrms stay L2-hot.
// Launch boundary guarantees invrms visibility -> __ldg is safe here.
// ---------------------------------------------------------------------------
__global__ __launch_bounds__(256) void kB(
    const float* __restrict__ x,
    const float* __restrict__ noise,
    const float* __restrict__ nw,
    float* __restrict__ out)
{
    const int b = blockIdx.x >> 9;
    const int c = blockIdx.x & (C_ - 1);
    const size_t plane = ((size_t)b * C_ + c) * HW_;

    const float4* xp = (const float4*)(x + plane);
    const float4* np = (const float4*)(noise + (size_t)b * HW_);
    const float4* ip = (const float4*)(g_invrms + b * HW_);
    const float w = __ldg(nw + c);
    const int tid = threadIdx.x;

    float4 y[4];
    float sum = 0.f, sumsq = 0.f;

#pragma unroll
    for (int j = 0; j < 4; j++) {
        const int i = tid + j * 256;
        const float4 xv = __ldcs(xp + i);
        const float4 nv = __ldg(np + i);
        const float4 iv = __ldg(ip + i);
        float4 yv;
        float v;
        v = fmaf(w, nv.x, xv.x); v = (v >= 0.f) ? v : 0.2f * v; yv.x = v * iv.x;
        v = fmaf(w, nv.y, xv.y); v = (v >= 0.f) ? v : 0.2f * v; yv.y = v * iv.y;
        v = fmaf(w, nv.z, xv.z); v = (v >= 0.f) ? v : 0.2f * v; yv.z = v * iv.z;
        v = fmaf(w, nv.w, xv.w); v = (v >= 0.f) ? v : 0.2f * v; yv.w = v * iv.w;
        y[j] = yv;
        sum   += yv.x + yv.y + yv.z + yv.w;
        sumsq += yv.x * yv.x + yv.y * yv.y + yv.z * yv.z + yv.w * yv.w;
    }

    const int lane = tid & 31, warp = tid >> 5;
#pragma unroll
    for (int off = 16; off > 0; off >>= 1) {
        sum   += __shfl_xor_sync(0xFFFFFFFFu, sum,   off);
        sumsq += __shfl_xor_sync(0xFFFFFFFFu, sumsq, off);
    }
    __shared__ float s_sum[8], s_sq[8], s_stats[2];
    if (lane == 0) { s_sum[warp] = sum; s_sq[warp] = sumsq; }
    __syncthreads();
    if (tid == 0) {
        float ts = 0.f, tq = 0.f;
#pragma unroll
        for (int k = 0; k < 8; k++) { ts += s_sum[k]; tq += s_sq[k]; }
        const float mean = ts * (1.f / (float)HW_);
        const float var  = tq * (1.f / (float)HW_) - mean * mean;
        s_stats[0] = mean;
        s_stats[1] = rsqrtf(var + 1e-5f);
    }
    __syncthreads();
    const float mean = s_stats[0];
    const float istd = s_stats[1];

    const float scale = g_style[b * 1024 + c] + 1.f;   // s[:,0] + 1
    const float shift = g_style[b * 1024 + C_ + c];    // s[:,1]
    const float a = istd * scale;
    const float d = shift - mean * a;

    float4* op = (float4*)(out + plane);
#pragma unroll
    for (int j = 0; j < 4; j++) {
        const int i = tid + j * 256;
        const float4 yv = y[j];
        float4 ov;
        ov.x = fmaf(yv.x, a, d);
        ov.y = fmaf(yv.y, a, d);
        ov.z = fmaf(yv.z, a, d);
        ov.w = fmaf(yv.w, a, d);
        __stcs(op + i, ov);
    }
}

// ---------------------------------------------------------------------------
// Inputs (metadata order): x, noise, style, noise_weight, lin_W, lin_b
// Output: float32 [B, C, H, W]
// ---------------------------------------------------------------------------
extern "C" void kernel_launch(void* const* d_in, const int* in_sizes, int n_in,
                              void* d_out, int out_size)
{
    const float* x     = (const float*)d_in[0];
    const float* noise = (const float*)d_in[1];
    const float* style = (const float*)d_in[2];
    const float* nw    = (const float*)d_in[3];
    const float* lin_W = (const float*)d_in[4];
    const float* lin_b = (const float*)d_in[5];
    float* out = (float*)d_out;

    kA<<<GEMM_BLOCKS + WORK_BLOCKS, 128>>>(x, noise, nw, style, lin_W, lin_b);
    kB<<<B_ * C_, 256>>>(x, noise, nw, out);
}